// round 6
// baseline (speedup 1.0000x reference)
#include <cuda_runtime.h>
#include <cuda_bf16.h>
#include <cstdint>

#define LOG2E 1.4426950408889634f
#define C1 (0.17677669529663687f * LOG2E)   // sm_scale * log2(e)

// smem layout (bytes)
#define OFF_MS 0                      // mask * log2e, 256 f32 (1024 B)
#define OFF_KH 1024                   // K hi bf16 [256][32], row stride 80 B
#define OFF_KL (OFF_KH + 256*80)      // K lo
#define OFF_VH (OFF_KL + 256*80)      // Vt hi bf16 [32][256], row stride 528 B
#define OFF_VL (OFF_VH + 32*528)      // Vt lo
#define SMEM_TOTAL (OFF_VL + 32*528)  // 75776 B
#define KLO_D (OFF_KL - OFF_KH)       // 20480
#define VLO_D (OFF_VL - OFF_VH)       // 16896

__device__ __forceinline__ float ex2f(float x) {
    float y; asm("ex2.approx.ftz.f32 %0, %1;" : "=f"(y) : "f"(x)); return y;
}
__device__ __forceinline__ uint32_t pack2(float a, float b) {
    __nv_bfloat162 t = __floats2bfloat162_rn(a, b);   // low half = a
    return *(uint32_t*)&t;
}
__device__ __forceinline__ void split2(float2 x, uint32_t& hi, uint32_t& lo) {
    __nv_bfloat162 hv = __floats2bfloat162_rn(x.x, x.y);
    float2 hf = __bfloat1622float2(hv);
    hi = *(uint32_t*)&hv;
    lo = pack2(x.x - hf.x, x.y - hf.y);
}
__device__ __forceinline__ void mma16816(float* d, const uint32_t* a,
                                         uint32_t b0, uint32_t b1) {
    asm volatile(
        "mma.sync.aligned.m16n8k16.row.col.f32.bf16.bf16.f32 "
        "{%0,%1,%2,%3}, {%4,%5,%6,%7}, {%8,%9}, {%0,%1,%2,%3};"
        : "+f"(d[0]), "+f"(d[1]), "+f"(d[2]), "+f"(d[3])
        : "r"(a[0]), "r"(a[1]), "r"(a[2]), "r"(a[3]), "r"(b0), "r"(b1));
}
__device__ __forceinline__ void ldsm4(uint32_t* r, uint32_t addr) {
    asm volatile("ldmatrix.sync.aligned.m8n8.x4.shared.b16 {%0,%1,%2,%3}, [%4];"
        : "=r"(r[0]), "=r"(r[1]), "=r"(r[2]), "=r"(r[3]) : "r"(addr));
}
__device__ __forceinline__ uint32_t smem_u32(const void* p) {
    uint32_t a;
    asm("{ .reg .u64 t; cvta.to.shared.u64 t, %1; cvt.u32.u64 %0, t; }" : "=r"(a) : "l"(p));
    return a;
}

// one 16-key tile: QK (3-product split) -> bias+exp2 -> PV (3-product split)
__device__ __forceinline__ void do_tile(
    int n0, uint32_t akA, uint32_t akB, uint32_t av1, uint32_t av2,
    const char* smem, const float* trow, const float* trow8, int c,
    const uint32_t (&qhi)[2][4], const uint32_t (&qlo)[2][4],
    float (&acc)[4][4], float& sum_g, float& sum_h)
{
    // triangle bias first (longest latency, L2-resident)
    float2 tA = *(const float2*)(trow  + n0 + c);
    float2 tB = *(const float2*)(trow  + n0 + 8 + c);
    float2 tC = *(const float2*)(trow8 + n0 + c);
    float2 tD = *(const float2*)(trow8 + n0 + 8 + c);

    // K fragments: one ldmatrix.x4 per (tile-half, hi/lo)
    uint32_t kAh[4], kAl[4], kBh[4], kBl[4];
    ldsm4(kAh, akA); ldsm4(kAl, akA + KLO_D);
    ldsm4(kBh, akB); ldsm4(kBl, akB + KLO_D);

    float d0[4] = {0.f, 0.f, 0.f, 0.f};
    float d1[4] = {0.f, 0.f, 0.f, 0.f};
    // regs {0,1} = kstep 0 (b0,b1), {2,3} = kstep 1
    mma16816(d0, qhi[0], kAh[0], kAh[1]);
    mma16816(d1, qhi[0], kBh[0], kBh[1]);
    mma16816(d0, qhi[1], kAh[2], kAh[3]);
    mma16816(d1, qhi[1], kBh[2], kBh[3]);
    mma16816(d0, qhi[0], kAl[0], kAl[1]);
    mma16816(d1, qhi[0], kBl[0], kBl[1]);
    mma16816(d0, qhi[1], kAl[2], kAl[3]);
    mma16816(d1, qhi[1], kBl[2], kBl[3]);
    mma16816(d0, qlo[0], kAh[0], kAh[1]);
    mma16816(d1, qlo[0], kBh[0], kBh[1]);
    mma16816(d0, qlo[1], kAh[2], kAh[3]);
    mma16816(d1, qlo[1], kBh[2], kBh[3]);

    // bias + exp2 (no max subtraction; fp32-safe)
    float2 msA = *(const float2*)(smem + OFF_MS + (n0 + c) * 4);
    float2 msB = *(const float2*)(smem + OFF_MS + (n0 + 8 + c) * 4);
    float e00 = ex2f(fmaf(d0[0], C1, fmaf(tA.x, LOG2E, msA.x)));
    float e01 = ex2f(fmaf(d0[1], C1, fmaf(tA.y, LOG2E, msA.y)));
    float e02 = ex2f(fmaf(d0[2], C1, fmaf(tC.x, LOG2E, msA.x)));
    float e03 = ex2f(fmaf(d0[3], C1, fmaf(tC.y, LOG2E, msA.y)));
    float e10 = ex2f(fmaf(d1[0], C1, fmaf(tB.x, LOG2E, msB.x)));
    float e11 = ex2f(fmaf(d1[1], C1, fmaf(tB.y, LOG2E, msB.y)));
    float e12 = ex2f(fmaf(d1[2], C1, fmaf(tD.x, LOG2E, msB.x)));
    float e13 = ex2f(fmaf(d1[3], C1, fmaf(tD.y, LOG2E, msB.y)));
    sum_g += (e00 + e01) + (e10 + e11);
    sum_h += (e02 + e03) + (e12 + e13);

    // P fragments (D-frag layout == A-frag layout)
    uint32_t ph[4], pl[4];
    { float2 x;
      x.x = e00; x.y = e01; split2(x, ph[0], pl[0]);
      x.x = e02; x.y = e03; split2(x, ph[1], pl[1]);
      x.x = e10; x.y = e11; split2(x, ph[2], pl[2]);
      x.x = e12; x.y = e13; split2(x, ph[3], pl[3]); }

    // V fragments: x4 covers two dn's (b0,b1 each)
    uint32_t vh1[4], vh2[4], vl1[4], vl2[4];
    ldsm4(vh1, av1); ldsm4(vh2, av2);
    ldsm4(vl1, av1 + VLO_D); ldsm4(vl2, av2 + VLO_D);

    mma16816(acc[0], ph, vh1[0], vh1[1]);
    mma16816(acc[1], ph, vh1[2], vh1[3]);
    mma16816(acc[2], ph, vh2[0], vh2[1]);
    mma16816(acc[3], ph, vh2[2], vh2[3]);
    mma16816(acc[0], ph, vl1[0], vl1[1]);
    mma16816(acc[1], ph, vl1[2], vl1[3]);
    mma16816(acc[2], ph, vl2[0], vl2[1]);
    mma16816(acc[3], ph, vl2[2], vl2[3]);
    mma16816(acc[0], pl, vh1[0], vh1[1]);
    mma16816(acc[1], pl, vh1[2], vh1[3]);
    mma16816(acc[2], pl, vh2[0], vh2[1]);
    mma16816(acc[3], pl, vh2[2], vh2[3]);
}

__global__ __launch_bounds__(256, 2)
void TFA_88089779241014_kernel(const float* __restrict__ q,
                               const float* __restrict__ k,
                               const float* __restrict__ v,
                               const float* __restrict__ mask,
                               const float* __restrict__ tri,
                               float* __restrict__ out) {
    extern __shared__ char smem[];

    const int tid  = threadIdx.x;
    const int lane = tid & 31;
    const int wid  = tid >> 5;
    const int g    = lane >> 2;
    const int c    = (lane & 3) * 2;

    const int bx   = blockIdx.x;        // head*2 + mtile
    const int head = bx >> 1;           // n*4 + h
    const int mt   = bx & 1;
    const int n    = head >> 2;
    const int h    = head & 3;

    const float* kb = k + (size_t)head * 8192;
    const float* vb = v + (size_t)head * 8192;
    const float* mb = mask + (size_t)n * 256;

    // ---- stage K as bf16 hi/lo, [t][d], 80B stride ----
    for (int i = tid; i < 4096; i += 256) {
        int t = i >> 4, c2 = (i & 15) << 1;
        float2 x = *(const float2*)(kb + t * 32 + c2);
        uint32_t hi, lo; split2(x, hi, lo);
        *(uint32_t*)(smem + OFF_KH + t * 80 + c2 * 2) = hi;
        *(uint32_t*)(smem + OFF_KL + t * 80 + c2 * 2) = lo;
    }
    // ---- stage V transposed: Vt[d][t], 528B stride ----
    for (int i = tid; i < 2048; i += 256) {
        float4 x = ((const float4*)vb)[i];
        int t = i >> 3, d4 = (i & 7) << 2;
        float e[4] = {x.x, x.y, x.z, x.w};
        #pragma unroll
        for (int j = 0; j < 4; j++) {
            int d = d4 + j;
            __nv_bfloat16 hv = __float2bfloat16_rn(e[j]);
            __nv_bfloat16 lv = __float2bfloat16_rn(e[j] - __bfloat162float(hv));
            *(__nv_bfloat16*)(smem + OFF_VH + d * 528 + t * 2) = hv;
            *(__nv_bfloat16*)(smem + OFF_VL + d * 528 + t * 2) = lv;
        }
    }
    for (int i = tid; i < 256; i += 256)
        *(float*)(smem + OFF_MS + i * 4) = mb[i] * LOG2E;

    // ---- Q fragments (registers, whole kernel) ----
    const int rowbase = mt * 128 + wid * 16;
    const float* qrow = q + (size_t)head * 8192 + (size_t)rowbase * 32;
    uint32_t qhi[2][4], qlo[2][4];
    #pragma unroll
    for (int s = 0; s < 2; s++) {
        int k0 = s * 16;
        split2(*(const float2*)(qrow + (g)     * 32 + k0 + c),     qhi[s][0], qlo[s][0]);
        split2(*(const float2*)(qrow + (g + 8) * 32 + k0 + c),     qhi[s][1], qlo[s][1]);
        split2(*(const float2*)(qrow + (g)     * 32 + k0 + 8 + c), qhi[s][2], qlo[s][2]);
        split2(*(const float2*)(qrow + (g + 8) * 32 + k0 + 8 + c), qhi[s][3], qlo[s][3]);
    }

    const float* trow  = tri + (size_t)h * 65536 + (size_t)(rowbase + g) * 256;
    const float* trow8 = trow + 8 * 256;

    // ---- per-lane ldmatrix base addresses ----
    const uint32_t sbu   = smem_u32(smem);
    const int lane7 = lane & 7, lh = lane >> 3;
    uint32_t akA = sbu + OFF_KH + (uint32_t)(lane7 * 80 + lh * 16);
    uint32_t akB = akA + 8 * 80;
    uint32_t av1 = sbu + OFF_VH + (uint32_t)(((lh >> 1) * 8 + lane7) * 528 + (lh & 1) * 16);
    uint32_t av2 = av1 + 16 * 528;

    __syncthreads();

    float acc[4][4];
    #pragma unroll
    for (int dn = 0; dn < 4; dn++)
        #pragma unroll
        for (int j = 0; j < 4; j++) acc[dn][j] = 0.f;
    float sum_g = 0.f, sum_h = 0.f;

    // ========== main loop: 2 independent 16-key tiles per iteration ==========
    #pragma unroll 1
    for (int it = 0; it < 8; it++) {
        const int n0 = it * 32;
        do_tile(n0,      akA,        akB,        av1,      av2,
                smem, trow, trow8, c, qhi, qlo, acc, sum_g, sum_h);
        do_tile(n0 + 16, akA + 1280, akB + 1280, av1 + 32, av2 + 32,
                smem, trow, trow8, c, qhi, qlo, acc, sum_g, sum_h);
        akA += 2560; akB += 2560; av1 += 64; av2 += 64;
    }

    // ---- row-sum reduce within quad ----
    sum_g += __shfl_xor_sync(0xffffffffu, sum_g, 1);
    sum_g += __shfl_xor_sync(0xffffffffu, sum_g, 2);
    sum_h += __shfl_xor_sync(0xffffffffu, sum_h, 1);
    sum_h += __shfl_xor_sync(0xffffffffu, sum_h, 2);
    const float rg = 1.f / sum_g;
    const float rh = 1.f / sum_h;

    // ---- store ----
    float* orow = out + (size_t)head * 8192 + (size_t)rowbase * 32;
    #pragma unroll
    for (int dn = 0; dn < 4; dn++) {
        float2 w0 = {acc[dn][0] * rg, acc[dn][1] * rg};
        float2 w1 = {acc[dn][2] * rh, acc[dn][3] * rh};
        *(float2*)(orow + (g)     * 32 + dn * 8 + c) = w0;
        *(float2*)(orow + (g + 8) * 32 + dn * 8 + c) = w1;
    }
}

extern "C" void kernel_launch(void* const* d_in, const int* in_sizes, int n_in,
                              void* d_out, int out_size) {
    const float* q    = (const float*)d_in[0];
    const float* k    = (const float*)d_in[1];
    const float* v    = (const float*)d_in[2];
    const float* mask = (const float*)d_in[3];
    const float* tri  = (const float*)d_in[4];
    float* out = (float*)d_out;

    cudaFuncSetAttribute(TFA_88089779241014_kernel,
                         cudaFuncAttributeMaxDynamicSharedMemorySize, SMEM_TOTAL);
    // 1024 heads x 2 query tiles of 128
    TFA_88089779241014_kernel<<<2048, 256, SMEM_TOTAL>>>(q, k, v, mask, tri, out);
}

// round 8
// speedup vs baseline: 1.1423x; 1.1423x over previous
#include <cuda_runtime.h>
#include <cuda_bf16.h>
#include <cstdint>

#define LOG2E 1.4426950408889634f
#define C1 (0.17677669529663687f * LOG2E)   // sm_scale * log2(e)

// smem layout (bytes) — compact, swizzled
#define OFF_MS 0                      // mask * log2e, 256 f32 (1024 B)
#define OFF_KH 1024                   // K hi bf16 [256][32], 64B rows, chunk-swizzled
#define OFF_KL (OFF_KH + 16384)      // K lo
#define OFF_VH (OFF_KL + 16384)      // Vt hi bf16 [32][256], 512B rows, swizzled
#define OFF_VL (OFF_VH + 16384)      // Vt lo
#define SMEM_TOTAL (OFF_VL + 16384)  // 66560 B

__device__ __forceinline__ float ex2f(float x) {
    float y; asm("ex2.approx.ftz.f32 %0, %1;" : "=f"(y) : "f"(x)); return y;
}
__device__ __forceinline__ uint32_t pack2(float a, float b) {
    __nv_bfloat162 t = __floats2bfloat162_rn(a, b);   // low half = a
    return *(uint32_t*)&t;
}
__device__ __forceinline__ void split2(float2 x, uint32_t& hi, uint32_t& lo) {
    __nv_bfloat162 hv = __floats2bfloat162_rn(x.x, x.y);
    float2 hf = __bfloat1622float2(hv);
    hi = *(uint32_t*)&hv;
    lo = pack2(x.x - hf.x, x.y - hf.y);
}
__device__ __forceinline__ void mma16816(float* d, const uint32_t* a,
                                         uint32_t b0, uint32_t b1) {
    asm volatile(
        "mma.sync.aligned.m16n8k16.row.col.f32.bf16.bf16.f32 "
        "{%0,%1,%2,%3}, {%4,%5,%6,%7}, {%8,%9}, {%0,%1,%2,%3};"
        : "+f"(d[0]), "+f"(d[1]), "+f"(d[2]), "+f"(d[3])
        : "r"(a[0]), "r"(a[1]), "r"(a[2]), "r"(a[3]), "r"(b0), "r"(b1));
}

__global__ __launch_bounds__(256, 3)
void TFA_88089779241014_kernel(const float* __restrict__ q,
                               const float* __restrict__ k,
                               const float* __restrict__ v,
                               const float* __restrict__ mask,
                               const float* __restrict__ tri,
                               float* __restrict__ out) {
    extern __shared__ char smem[];

    const int tid  = threadIdx.x;
    const int lane = tid & 31;
    const int wid  = tid >> 5;
    const int g    = lane >> 2;
    const int tg   = lane & 3;
    const int c    = tg * 2;

    const int bx   = blockIdx.x;        // head*2 + mtile
    const int head = bx >> 1;           // n*4 + h
    const int mt   = bx & 1;
    const int n    = head >> 2;
    const int h    = head & 3;

    const float* kb = k + (size_t)head * 8192;
    const float* vb = v + (size_t)head * 8192;
    const float* mb = mask + (size_t)n * 256;

    // ---- stage K as bf16 hi/lo, [t][d], 64B rows, swizzle b ^= ((t>>1)&3)<<4 ----
    for (int i = tid; i < 4096; i += 256) {
        int t = i >> 4;
        int b0 = (i & 15) * 4;
        float2 x = *(const float2*)(kb + t * 32 + (i & 15) * 2);
        uint32_t hi, lo; split2(x, hi, lo);
        int b = b0 ^ (((t >> 1) & 3) << 4);
        *(uint32_t*)(smem + OFF_KH + t * 64 + b) = hi;
        *(uint32_t*)(smem + OFF_KL + t * 64 + b) = lo;
    }
    // ---- stage V transposed: Vt[d][t], 512B rows, swizzle b ^= (d&7)<<4 ----
    for (int i = tid; i < 2048; i += 256) {
        float4 x = ((const float4*)vb)[i];
        int t = i >> 3, d4 = (i & 7) << 2;
        float e[4] = {x.x, x.y, x.z, x.w};
        #pragma unroll
        for (int j = 0; j < 4; j++) {
            int d = d4 + j;
            __nv_bfloat16 hv = __float2bfloat16_rn(e[j]);
            __nv_bfloat16 lv = __float2bfloat16_rn(e[j] - __bfloat162float(hv));
            int b = (t * 2) ^ ((d & 7) << 4);
            *(__nv_bfloat16*)(smem + OFF_VH + d * 512 + b) = hv;
            *(__nv_bfloat16*)(smem + OFF_VL + d * 512 + b) = lv;
        }
    }
    for (int i = tid; i < 256; i += 256)
        *(float*)(smem + OFF_MS + i * 4) = mb[i] * LOG2E;

    // ---- Q fragments (registers, whole kernel) ----
    const int rowbase = mt * 128 + wid * 16;
    const float* qrow = q + (size_t)head * 8192 + (size_t)rowbase * 32;
    uint32_t qhi[2][4], qlo[2][4];
    #pragma unroll
    for (int s = 0; s < 2; s++) {
        int k0 = s * 16;
        split2(*(const float2*)(qrow + (g)     * 32 + k0 + c),     qhi[s][0], qlo[s][0]);
        split2(*(const float2*)(qrow + (g + 8) * 32 + k0 + c),     qhi[s][1], qlo[s][1]);
        split2(*(const float2*)(qrow + (g)     * 32 + k0 + 8 + c), qhi[s][2], qlo[s][2]);
        split2(*(const float2*)(qrow + (g + 8) * 32 + k0 + 8 + c), qhi[s][3], qlo[s][3]);
    }

    const float* trow  = tri + (size_t)h * 65536 + (size_t)(rowbase + g) * 256;
    const float* trow8 = trow + 8 * 256;

    // lane-constant swizzle offsets
    const int sK  = ((g >> 1) & 3) << 4;           // K row-pair swizzle (same for g and g+8)
    const int o00 = sK, o01 = sK ^ 16, o10 = sK ^ 32, o11 = sK ^ 48;
    // V low-bit offsets: b0 fragment (keys +0..) and b1 fragment (keys +8..)
    // swizzle bit4 ((g&1)<<4) must be XORed INTO the +16, not added after.
    const int vlc0 = (tg * 4)      ^ ((g & 1) << 4);
    const int vlc1 = (tg * 4 + 16) ^ ((g & 1) << 4);
    const int gx   = (g >> 1) << 5;                // V per-tile XOR term (bits 5-6)

    __syncthreads();

    float acc[4][4];
    #pragma unroll
    for (int dn = 0; dn < 4; dn++)
        #pragma unroll
        for (int j = 0; j < 4; j++) acc[dn][j] = 0.f;
    float sum_g = 0.f, sum_h = 0.f;

    // ================= main loop over 16-key tiles =================
    #pragma unroll 1
    for (int kt = 0; kt < 16; kt++) {
        const int n0 = kt * 16;

        // triangle bias first (longest latency, L2-resident)
        float2 tA = *(const float2*)(trow  + n0 + c);
        float2 tB = *(const float2*)(trow  + n0 + 8 + c);
        float2 tC = *(const float2*)(trow8 + n0 + c);
        float2 tD = *(const float2*)(trow8 + n0 + 8 + c);

        // K row pointers (swizzled, lane-constant XOR folded into o??)
        const char* kA = smem + (n0 + g)     * 64 + tg * 4;
        const char* kB = smem + (n0 + 8 + g) * 64 + tg * 4;

        float d0[4] = {0.f, 0.f, 0.f, 0.f};
        float d1[4] = {0.f, 0.f, 0.f, 0.f};
        #pragma unroll
        for (int s = 0; s < 2; s++) {
            const int oa = s ? o10 : o00;
            const int ob = s ? o11 : o01;
            uint32_t bAh0 = *(const uint32_t*)(kA + OFF_KH + oa);
            uint32_t bAh1 = *(const uint32_t*)(kA + OFF_KH + ob);
            uint32_t bAl0 = *(const uint32_t*)(kA + OFF_KL + oa);
            uint32_t bAl1 = *(const uint32_t*)(kA + OFF_KL + ob);
            uint32_t bBh0 = *(const uint32_t*)(kB + OFF_KH + oa);
            uint32_t bBh1 = *(const uint32_t*)(kB + OFF_KH + ob);
            uint32_t bBl0 = *(const uint32_t*)(kB + OFF_KL + oa);
            uint32_t bBl1 = *(const uint32_t*)(kB + OFF_KL + ob);
            mma16816(d0, qhi[s], bAh0, bAh1);
            mma16816(d0, qhi[s], bAl0, bAl1);
            mma16816(d0, qlo[s], bAh0, bAh1);
            mma16816(d1, qhi[s], bBh0, bBh1);
            mma16816(d1, qhi[s], bBl0, bBl1);
            mma16816(d1, qlo[s], bBh0, bBh1);
        }

        // bias + exp2 (no max subtraction; fp32-safe)
        float2 msA = *(const float2*)(smem + OFF_MS + (n0 + c) * 4);
        float2 msB = *(const float2*)(smem + OFF_MS + (n0 + 8 + c) * 4);
        float e00 = ex2f(fmaf(d0[0], C1, fmaf(tA.x, LOG2E, msA.x)));
        float e01 = ex2f(fmaf(d0[1], C1, fmaf(tA.y, LOG2E, msA.y)));
        float e02 = ex2f(fmaf(d0[2], C1, fmaf(tC.x, LOG2E, msA.x)));
        float e03 = ex2f(fmaf(d0[3], C1, fmaf(tC.y, LOG2E, msA.y)));
        float e10 = ex2f(fmaf(d1[0], C1, fmaf(tB.x, LOG2E, msB.x)));
        float e11 = ex2f(fmaf(d1[1], C1, fmaf(tB.y, LOG2E, msB.y)));
        float e12 = ex2f(fmaf(d1[2], C1, fmaf(tD.x, LOG2E, msB.x)));
        float e13 = ex2f(fmaf(d1[3], C1, fmaf(tD.y, LOG2E, msB.y)));
        sum_g += (e00 + e01) + (e10 + e11);
        sum_h += (e02 + e03) + (e12 + e13);

        // P fragments (D-frag layout == A-frag layout)
        uint32_t ph[4], pl[4];
        { float2 x;
          x.x = e00; x.y = e01; split2(x, ph[0], pl[0]);
          x.x = e02; x.y = e03; split2(x, ph[1], pl[1]);
          x.x = e10; x.y = e11; split2(x, ph[2], pl[2]);
          x.x = e12; x.y = e13; split2(x, ph[3], pl[3]); }

        // PV: out[16 x 32] += P[16 x 16] * V[16keys x 32]
        const int tcol = (n0 * 2) ^ gx;            // per-tile V column (swizzled hi bits)
        #pragma unroll
        for (int dn = 0; dn < 4; dn++) {
            const char* vrow = smem + (dn * 8 + g) * 512 + tcol;
            uint32_t vh0 = *(const uint32_t*)(vrow + OFF_VH + vlc0);
            uint32_t vh1 = *(const uint32_t*)(vrow + OFF_VH + vlc1);
            uint32_t vl0 = *(const uint32_t*)(vrow + OFF_VL + vlc0);
            uint32_t vl1 = *(const uint32_t*)(vrow + OFF_VL + vlc1);
            mma16816(acc[dn], ph, vh0, vh1);
            mma16816(acc[dn], ph, vl0, vl1);
            mma16816(acc[dn], pl, vh0, vh1);
        }
    }

    // ---- row-sum reduce within quad ----
    sum_g += __shfl_xor_sync(0xffffffffu, sum_g, 1);
    sum_g += __shfl_xor_sync(0xffffffffu, sum_g, 2);
    sum_h += __shfl_xor_sync(0xffffffffu, sum_h, 1);
    sum_h += __shfl_xor_sync(0xffffffffu, sum_h, 2);
    const float rg = 1.f / sum_g;
    const float rh = 1.f / sum_h;

    // ---- store ----
    float* orow = out + (size_t)head * 8192 + (size_t)rowbase * 32;
    #pragma unroll
    for (int dn = 0; dn < 4; dn++) {
        float2 w0 = {acc[dn][0] * rg, acc[dn][1] * rg};
        float2 w1 = {acc[dn][2] * rh, acc[dn][3] * rh};
        *(float2*)(orow + (g)     * 32 + dn * 8 + c) = w0;
        *(float2*)(orow + (g + 8) * 32 + dn * 8 + c) = w1;
    }
}

extern "C" void kernel_launch(void* const* d_in, const int* in_sizes, int n_in,
                              void* d_out, int out_size) {
    const float* q    = (const float*)d_in[0];
    const float* k    = (const float*)d_in[1];
    const float* v    = (const float*)d_in[2];
    const float* mask = (const float*)d_in[3];
    const float* tri  = (const float*)d_in[4];
    float* out = (float*)d_out;

    cudaFuncSetAttribute(TFA_88089779241014_kernel,
                         cudaFuncAttributeMaxDynamicSharedMemorySize, SMEM_TOTAL);
    // 1024 heads x 2 query tiles of 128
    TFA_88089779241014_kernel<<<2048, 256, SMEM_TOTAL>>>(q, k, v, mask, tri, out);
}